// round 6
// baseline (speedup 1.0000x reference)
#include <cuda_runtime.h>
#include <cstdint>

#define SS 4096
#define DD 1024
#define HH 16
#define DHH 64
#define SCALE_INV 0.03125f                 // 1/sqrt(1024)
#define SCALE_L2E 0.045111762f             // SCALE_INV * log2(e)

__device__ __forceinline__ uint32_t f2tf(float f) {
    uint32_t r; asm("cvt.rna.tf32.f32 %0, %1;" : "=r"(r) : "f"(f)); return r;
}
__device__ __forceinline__ float ex2f(float x) {
    float r; asm("ex2.approx.f32 %0, %1;" : "=f"(r) : "f"(x)); return r;
}
__device__ __forceinline__ void mma_tf32(float* d, const uint32_t* a,
                                         uint32_t b0, uint32_t b1) {
    asm volatile(
        "mma.sync.aligned.m16n8k8.row.col.f32.tf32.tf32.f32 "
        "{%0,%1,%2,%3}, {%4,%5,%6,%7}, {%8,%9}, {%0,%1,%2,%3};"
        : "+f"(d[0]), "+f"(d[1]), "+f"(d[2]), "+f"(d[3])
        : "r"(a[0]), "r"(a[1]), "r"(a[2]), "r"(a[3]), "r"(b0), "r"(b1));
}

// Scratch
__device__ float g_Q[HH * SS * DHH];
__device__ float g_K[HH * SS * DHH];
__device__ float g_V[HH * SS * DHH];
__device__ float g_O[HH * SS * DHH];
// Transposed tf32 weights: 64 slabs of [64][1024].
__device__ uint32_t g_WT[64 * 64 * 1024];

// ---------------------------------------------------------------------------
// Weight pre-transpose: W[d][e] -> g_WT[slab][e][d] (tf32 bits)
// ---------------------------------------------------------------------------
__global__ __launch_bounds__(256) void transpose_w(
    const float* __restrict__ Wq, const float* __restrict__ Wk,
    const float* __restrict__ Wv, const float* __restrict__ Wo)
{
    __shared__ float tile[32][33];
    const int slab = blockIdx.z, which = slab >> 4, hh = slab & 15;
    const float* src; int ld; size_t off;
    if (which == 0)      { src = Wq; ld = DHH; off = (size_t)hh * DD * DHH; }
    else if (which == 1) { src = Wk; ld = DHH; off = (size_t)hh * DD * DHH; }
    else if (which == 2) { src = Wv; ld = DHH; off = (size_t)hh * DD * DHH; }
    else                 { src = Wo; ld = DD;  off = (size_t)hh * 64; }
    const int d0 = blockIdx.x * 32, e0 = blockIdx.y * 32;
    const int tx = threadIdx.x, ty = threadIdx.y;
    #pragma unroll
    for (int j = 0; j < 32; j += 8)
        tile[ty + j][tx] = src[off + (size_t)(d0 + ty + j) * ld + e0 + tx];
    __syncthreads();
    uint32_t* dst = g_WT + (size_t)slab * 65536;
    #pragma unroll
    for (int j = 0; j < 32; j += 8)
        dst[(size_t)(e0 + ty + j) * 1024 + d0 + tx] = f2tf(tile[tx][ty + j]);
}

// ---------------------------------------------------------------------------
// Shared GEMM body: C[128 x 64] = A[128 x 1024] * WT^T, double-buffered.
// smem layout (uint32): As0[128*68], As1[128*68], Ws0[64*68], Ws1[64*68]
// ---------------------------------------------------------------------------
#define PROJ_SMEM ((2 * 128 * 68 + 2 * 64 * 68) * 4)

struct ProjSrc {
    const float* A;   // row base (A + m0*ldA)
    int ldA;          // 1024 for q/k/v; DHH for g_O heads (with per-chunk base)
};

// ---------------------------------------------------------------------------
// QKV projection. CTA = (128 s-rows, head, which). Double-buffered chunks.
// ---------------------------------------------------------------------------
__global__ __launch_bounds__(256, 2) void proj_mma_kernel(
    const float* __restrict__ q, const float* __restrict__ k,
    const float* __restrict__ v,
    const float* __restrict__ bq, const float* __restrict__ bk,
    const float* __restrict__ bv)
{
    extern __shared__ uint32_t sm[];
    uint32_t* Asb[2] = { sm, sm + 128 * 68 };
    uint32_t* Wsb[2] = { sm + 2 * 128 * 68, sm + 2 * 128 * 68 + 64 * 68 };

    const int z  = blockIdx.z;
    const int h  = blockIdx.y;
    const int m0 = blockIdx.x * 128;
    const float* A     = (z == 0) ? q : (z == 1) ? k : v;
    const float* biasp = ((z == 0) ? bq : (z == 1) ? bk : bv) + h * DHH;
    float* out = ((z == 0) ? g_Q : (z == 1) ? g_K : g_V) + (size_t)h * SS * DHH;
    const uint32_t* WT = g_WT + (size_t)(z * 16 + h) * 65536;

    const int t = threadIdx.x, wid = t >> 5, lane = t & 31;
    const int m0w = (wid >> 1) * 32, n0w = (wid & 1) * 32;
    const int lq = lane >> 2, ll = lane & 3;

    auto load_chunk = [&](int kc, uint32_t* As, uint32_t* Ws) {
        const int k0 = kc * 64;
        #pragma unroll
        for (int it = 0; it < 8; it++) {
            int idx = t + it * 256;
            int r = idx >> 4, c4 = (idx & 15) * 4;
            float4 vv = *(const float4*)(A + (size_t)(m0 + r) * DD + k0 + c4);
            uint4 u;
            u.x = f2tf(vv.x); u.y = f2tf(vv.y); u.z = f2tf(vv.z); u.w = f2tf(vv.w);
            *(uint4*)(As + r * 68 + c4) = u;
        }
        #pragma unroll
        for (int it = 0; it < 4; it++) {
            int idx = t + it * 256;
            int e = idx >> 4, k4 = (idx & 15) * 4;
            *(uint4*)(Ws + e * 68 + k4) =
                *(const uint4*)(WT + (size_t)e * 1024 + k0 + k4);
        }
    };

    float c[2][4][4] = {};
    load_chunk(0, Asb[0], Wsb[0]);
    __syncthreads();

    for (int kc = 0; kc < 16; kc++) {
        const int cur = kc & 1;
        uint32_t* As = Asb[cur];
        uint32_t* Ws = Wsb[cur];
        #pragma unroll
        for (int ks = 0; ks < 8; ks++) {
            uint32_t a[2][4];
            #pragma unroll
            for (int mt = 0; mt < 2; mt++) {
                int row = m0w + mt * 16 + lq, col = ks * 8 + ll;
                a[mt][0] = As[row * 68 + col];
                a[mt][1] = As[(row + 8) * 68 + col];
                a[mt][2] = As[row * 68 + col + 4];
                a[mt][3] = As[(row + 8) * 68 + col + 4];
            }
            #pragma unroll
            for (int nt = 0; nt < 4; nt++) {
                int nrow = n0w + nt * 8 + lq, col = ks * 8 + ll;
                uint32_t b0 = Ws[nrow * 68 + col];
                uint32_t b1 = Ws[nrow * 68 + col + 4];
                mma_tf32(c[0][nt], a[0], b0, b1);
                mma_tf32(c[1][nt], a[1], b0, b1);
            }
        }
        if (kc < 15) load_chunk(kc + 1, Asb[cur ^ 1], Wsb[cur ^ 1]);
        __syncthreads();
    }

    #pragma unroll
    for (int mt = 0; mt < 2; mt++) {
        int row = m0w + mt * 16 + lq;
        #pragma unroll
        for (int nt = 0; nt < 4; nt++) {
            int col = n0w + nt * 8 + 2 * ll;
            float2 o0 = make_float2(c[mt][nt][0] + biasp[col],
                                    c[mt][nt][1] + biasp[col + 1]);
            float2 o1 = make_float2(c[mt][nt][2] + biasp[col],
                                    c[mt][nt][3] + biasp[col + 1]);
            *(float2*)(out + (size_t)(m0 + row) * DHH + col) = o0;
            *(float2*)(out + (size_t)(m0 + row + 8) * DHH + col) = o1;
        }
    }
}

// ---------------------------------------------------------------------------
// Output projection, double-buffered. Chunk kc == head (gather from g_O).
// ---------------------------------------------------------------------------
__global__ __launch_bounds__(256, 2) void outproj_mma_kernel(
    const float* __restrict__ bo, float* __restrict__ Cout)
{
    extern __shared__ uint32_t sm[];
    uint32_t* Asb[2] = { sm, sm + 128 * 68 };
    uint32_t* Wsb[2] = { sm + 2 * 128 * 68, sm + 2 * 128 * 68 + 64 * 68 };

    const int m0 = blockIdx.x * 128;
    const int n0 = blockIdx.y * 64;
    const uint32_t* WT = g_WT + (size_t)(48 + blockIdx.y) * 65536;
    const float* biasp = bo + n0;

    const int t = threadIdx.x, wid = t >> 5, lane = t & 31;
    const int m0w = (wid >> 1) * 32, n0w = (wid & 1) * 32;
    const int lq = lane >> 2, ll = lane & 3;

    auto load_chunk = [&](int kc, uint32_t* As, uint32_t* Ws) {
        const int k0 = kc * 64;
        const float* A = g_O + (size_t)kc * SS * DHH;
        #pragma unroll
        for (int it = 0; it < 8; it++) {
            int idx = t + it * 256;
            int r = idx >> 4, c4 = (idx & 15) * 4;
            float4 vv = *(const float4*)(A + (size_t)(m0 + r) * DHH + c4);
            uint4 u;
            u.x = f2tf(vv.x); u.y = f2tf(vv.y); u.z = f2tf(vv.z); u.w = f2tf(vv.w);
            *(uint4*)(As + r * 68 + c4) = u;
        }
        #pragma unroll
        for (int it = 0; it < 4; it++) {
            int idx = t + it * 256;
            int e = idx >> 4, k4 = (idx & 15) * 4;
            *(uint4*)(Ws + e * 68 + k4) =
                *(const uint4*)(WT + (size_t)e * 1024 + k0 + k4);
        }
    };

    float c[2][4][4] = {};
    load_chunk(0, Asb[0], Wsb[0]);
    __syncthreads();

    for (int kc = 0; kc < 16; kc++) {
        const int cur = kc & 1;
        uint32_t* As = Asb[cur];
        uint32_t* Ws = Wsb[cur];
        #pragma unroll
        for (int ks = 0; ks < 8; ks++) {
            uint32_t a[2][4];
            #pragma unroll
            for (int mt = 0; mt < 2; mt++) {
                int row = m0w + mt * 16 + lq, col = ks * 8 + ll;
                a[mt][0] = As[row * 68 + col];
                a[mt][1] = As[(row + 8) * 68 + col];
                a[mt][2] = As[row * 68 + col + 4];
                a[mt][3] = As[(row + 8) * 68 + col + 4];
            }
            #pragma unroll
            for (int nt = 0; nt < 4; nt++) {
                int nrow = n0w + nt * 8 + lq, col = ks * 8 + ll;
                uint32_t b0 = Ws[nrow * 68 + col];
                uint32_t b1 = Ws[nrow * 68 + col + 4];
                mma_tf32(c[0][nt], a[0], b0, b1);
                mma_tf32(c[1][nt], a[1], b0, b1);
            }
        }
        if (kc < 15) load_chunk(kc + 1, Asb[cur ^ 1], Wsb[cur ^ 1]);
        __syncthreads();
    }

    #pragma unroll
    for (int mt = 0; mt < 2; mt++) {
        int row = m0w + mt * 16 + lq;
        #pragma unroll
        for (int nt = 0; nt < 4; nt++) {
            int col = n0w + nt * 8 + 2 * ll;
            float2 o0 = make_float2(c[mt][nt][0] + biasp[col],
                                    c[mt][nt][1] + biasp[col + 1]);
            float2 o1 = make_float2(c[mt][nt][2] + biasp[col],
                                    c[mt][nt][3] + biasp[col + 1]);
            *(float2*)(Cout + (size_t)(m0 + row) * DD + n0 + col) = o0;
            *(float2*)(Cout + (size_t)(m0 + row + 8) * DD + n0 + col) = o1;
        }
    }
}

// ---------------------------------------------------------------------------
// Flash attention on mma.sync tf32, double-buffered K/V.
// smem (uint32): Qs[8704] | Ks0[8704] | Ks1[8704] | Vs0[9216] | Vs1[9216]
// Epilogue reuse: lred @0, Opart @8704.
// Q pre-scaled by SCALE_INV*log2(e); P = ex2(S).
// ---------------------------------------------------------------------------
#define ATTN_SMEM ((8704 * 3 + 9216 * 2) * 4)

__global__ __launch_bounds__(256, 1) void attn_kernel()
{
    extern __shared__ uint32_t smu[];
    uint32_t* Qs = smu;
    uint32_t* Ksb[2] = { smu + 8704, smu + 17408 };
    uint32_t* Vsb[2] = { smu + 26112, smu + 35328 };
    float* lred  = (float*)smu;            // [2][128]
    float* Opart = (float*)(smu + 8704);   // [128][68]

    const int t      = threadIdx.x;
    const int wid    = t >> 5;
    const int lane   = t & 31;
    const int warp_n = wid & 1;
    const int m0w    = (wid >> 1) * 32;
    const int n0w    = warp_n * 64;
    const int lq     = lane >> 2;
    const int ll     = lane & 3;

    const int m0 = blockIdx.x * 128;
    const int h  = blockIdx.y;
    const float* Qg = g_Q + (size_t)h * SS * DHH;
    const float* Kg = g_K + (size_t)h * SS * DHH;
    const float* Vg = g_V + (size_t)h * SS * DHH;

    auto load_kv = [&](int kb0, uint32_t* Kd, uint32_t* Vd) {
        #pragma unroll
        for (int it = 0; it < 8; it++) {
            int idx = t + it * 256;
            int r = idx >> 4, c4 = (idx & 15) * 4;
            float4 v = *(const float4*)(Kg + (size_t)(kb0 + r) * DHH + c4);
            uint32_t* dst = Kd + r * 68 + c4;
            dst[0] = f2tf(v.x); dst[1] = f2tf(v.y);
            dst[2] = f2tf(v.z); dst[3] = f2tf(v.w);
        }
        #pragma unroll
        for (int it = 0; it < 8; it++) {
            int idx = t + it * 256;
            int kk = idx >> 4, e4 = (idx & 15) * 4;
            int pos = (kk & 0x78) | (((kk & 7) >> 1) + ((kk & 1) << 2));
            float4 v = *(const float4*)(Vg + (size_t)(kb0 + kk) * DHH + e4);
            uint32_t* dst = Vd + pos * 72 + e4;
            dst[0] = f2tf(v.x); dst[1] = f2tf(v.y);
            dst[2] = f2tf(v.z); dst[3] = f2tf(v.w);
        }
    };

    // Fill Qs (scaled by 1/32 * log2e, tf32)
    #pragma unroll
    for (int it = 0; it < 8; it++) {
        int idx = t + it * 256;
        int r = idx >> 4, c4 = (idx & 15) * 4;
        float4 v = *(const float4*)(Qg + (size_t)(m0 + r) * DHH + c4);
        uint32_t* dst = Qs + r * 68 + c4;
        dst[0] = f2tf(v.x * SCALE_L2E);
        dst[1] = f2tf(v.y * SCALE_L2E);
        dst[2] = f2tf(v.z * SCALE_L2E);
        dst[3] = f2tf(v.w * SCALE_L2E);
    }
    load_kv(0, Ksb[0], Vsb[0]);

    float oC[2][8][4];
    #pragma unroll
    for (int mt = 0; mt < 2; mt++)
        #pragma unroll
        for (int nt = 0; nt < 8; nt++)
            #pragma unroll
            for (int i = 0; i < 4; i++) oC[mt][nt][i] = 0.0f;
    float lacc[2][2] = {};

    __syncthreads();

    for (int kt = 0; kt < 32; kt++) {
        const int cur = kt & 1;
        uint32_t* Ks = Ksb[cur];
        uint32_t* Vs = Vsb[cur];

        float sC[2][8][4];
        #pragma unroll
        for (int mt = 0; mt < 2; mt++)
            #pragma unroll
            for (int nt = 0; nt < 8; nt++)
                #pragma unroll
                for (int i = 0; i < 4; i++) sC[mt][nt][i] = 0.0f;

        #pragma unroll
        for (int ks = 0; ks < 8; ks++) {
            uint32_t a[2][4];
            #pragma unroll
            for (int mt = 0; mt < 2; mt++) {
                int row = m0w + mt * 16 + lq;
                int col = ks * 8 + ll;
                a[mt][0] = Qs[row * 68 + col];
                a[mt][1] = Qs[(row + 8) * 68 + col];
                a[mt][2] = Qs[row * 68 + col + 4];
                a[mt][3] = Qs[(row + 8) * 68 + col + 4];
            }
            #pragma unroll
            for (int nt = 0; nt < 8; nt++) {
                int krow = n0w + nt * 8 + lq;
                int kcol = ks * 8 + ll;
                uint32_t b0 = Ks[krow * 68 + kcol];
                uint32_t b1 = Ks[krow * 68 + kcol + 4];
                mma_tf32(sC[0][nt], a[0], b0, b1);
                mma_tf32(sC[1][nt], a[1], b0, b1);
            }
        }

        // P = 2^S (S already includes log2e), accumulate row sums
        #pragma unroll
        for (int mt = 0; mt < 2; mt++)
            #pragma unroll
            for (int nt = 0; nt < 8; nt++)
                #pragma unroll
                for (int i = 0; i < 4; i++) {
                    float p = ex2f(sC[mt][nt][i]);
                    lacc[mt][i >> 1] += p;
                    sC[mt][nt][i] = __uint_as_float(f2tf(p));
                }

        // O += P V
        #pragma unroll
        for (int ks = 0; ks < 8; ks++) {
            uint32_t A0[4] = { __float_as_uint(sC[0][ks][0]),
                               __float_as_uint(sC[0][ks][2]),
                               __float_as_uint(sC[0][ks][1]),
                               __float_as_uint(sC[0][ks][3]) };
            uint32_t A1[4] = { __float_as_uint(sC[1][ks][0]),
                               __float_as_uint(sC[1][ks][2]),
                               __float_as_uint(sC[1][ks][1]),
                               __float_as_uint(sC[1][ks][3]) };
            int posb = n0w + ks * 8 + ll;
            #pragma unroll
            for (int nt2 = 0; nt2 < 8; nt2++) {
                int e = nt2 * 8 + lq;
                uint32_t b0 = Vs[posb * 72 + e];
                uint32_t b1 = Vs[(posb + 4) * 72 + e];
                mma_tf32(oC[0][nt2], A0, b0, b1);
                mma_tf32(oC[1][nt2], A1, b0, b1);
            }
        }

        if (kt < 31) load_kv((kt + 1) * 128, Ksb[cur ^ 1], Vsb[cur ^ 1]);
        __syncthreads();
    }

    // Row sums: quad-reduce then publish per n-half
    #pragma unroll
    for (int mt = 0; mt < 2; mt++)
        #pragma unroll
        for (int half = 0; half < 2; half++) {
            float ls = lacc[mt][half];
            ls += __shfl_xor_sync(0xffffffffu, ls, 1);
            ls += __shfl_xor_sync(0xffffffffu, ls, 2);
            if (ll == 0) {
                int row = m0w + mt * 16 + half * 8 + lq;
                lred[warp_n * 128 + row] = ls;
            }
        }
    if (warp_n == 1) {
        #pragma unroll
        for (int mt = 0; mt < 2; mt++)
            #pragma unroll
            for (int nt2 = 0; nt2 < 8; nt2++) {
                int row = m0w + mt * 16 + lq;
                int col = nt2 * 8 + 2 * ll;
                *(float2*)(Opart + row * 68 + col) =
                    make_float2(oC[mt][nt2][0], oC[mt][nt2][1]);
                *(float2*)(Opart + (row + 8) * 68 + col) =
                    make_float2(oC[mt][nt2][2], oC[mt][nt2][3]);
            }
    }
    __syncthreads();

    if (warp_n == 0) {
        float* Og = g_O + (size_t)h * SS * DHH;
        #pragma unroll
        for (int mt = 0; mt < 2; mt++) {
            int row = m0w + mt * 16 + lq;
            float li0 = 1.0f / (lred[row] + lred[128 + row]);
            float li1 = 1.0f / (lred[row + 8] + lred[128 + row + 8]);
            #pragma unroll
            for (int nt2 = 0; nt2 < 8; nt2++) {
                int col = nt2 * 8 + 2 * ll;
                float2 p0 = *(float2*)(Opart + row * 68 + col);
                float2 p1 = *(float2*)(Opart + (row + 8) * 68 + col);
                float2 o0 = make_float2((oC[mt][nt2][0] + p0.x) * li0,
                                        (oC[mt][nt2][1] + p0.y) * li0);
                float2 o1 = make_float2((oC[mt][nt2][2] + p1.x) * li1,
                                        (oC[mt][nt2][3] + p1.y) * li1);
                *(float2*)(Og + (size_t)(m0 + row) * DHH + col) = o0;
                *(float2*)(Og + (size_t)(m0 + row + 8) * DHH + col) = o1;
            }
        }
    }
}

// ---------------------------------------------------------------------------
extern "C" void kernel_launch(void* const* d_in, const int* in_sizes, int n_in,
                              void* d_out, int out_size)
{
    const float* q  = (const float*)d_in[0];
    const float* k  = (const float*)d_in[1];
    const float* v  = (const float*)d_in[2];
    const float* Wq = (const float*)d_in[3];
    const float* bq = (const float*)d_in[4];
    const float* Wk = (const float*)d_in[5];
    const float* bk = (const float*)d_in[6];
    const float* Wv = (const float*)d_in[7];
    const float* bv = (const float*)d_in[8];
    const float* Wo = (const float*)d_in[9];
    const float* bo = (const float*)d_in[10];
    float* out = (float*)d_out;

    transpose_w<<<dim3(32, 2, 64), dim3(32, 8)>>>(Wq, Wk, Wv, Wo);

    cudaFuncSetAttribute(proj_mma_kernel,
                         cudaFuncAttributeMaxDynamicSharedMemorySize, PROJ_SMEM);
    proj_mma_kernel<<<dim3(SS / 128, HH, 3), 256, PROJ_SMEM>>>(
        q, k, v, bq, bk, bv);

    cudaFuncSetAttribute(attn_kernel,
                         cudaFuncAttributeMaxDynamicSharedMemorySize, ATTN_SMEM);
    attn_kernel<<<dim3(SS / 128, HH), 256, ATTN_SMEM>>>();

    cudaFuncSetAttribute(outproj_mma_kernel,
                         cudaFuncAttributeMaxDynamicSharedMemorySize, PROJ_SMEM);
    outproj_mma_kernel<<<dim3(SS / 128, DD / 64), 256, PROJ_SMEM>>>(bo, out);
}

// round 7
// speedup vs baseline: 1.5909x; 1.5909x over previous
#include <cuda_runtime.h>
#include <cstdint>

#define SS 4096
#define DD 1024
#define HH 16
#define DHH 64
#define SCALE_L2E 0.045111762f             // (1/32) * log2(e)

__device__ __forceinline__ uint32_t f2tf(float f) {
    uint32_t r; asm("cvt.rna.tf32.f32 %0, %1;" : "=r"(r) : "f"(f)); return r;
}
__device__ __forceinline__ float ex2f(float x) {
    float r; asm("ex2.approx.f32 %0, %1;" : "=f"(r) : "f"(x)); return r;
}
__device__ __forceinline__ void mma_tf32(float* d, const uint32_t* a,
                                         uint32_t b0, uint32_t b1) {
    asm volatile(
        "mma.sync.aligned.m16n8k8.row.col.f32.tf32.tf32.f32 "
        "{%0,%1,%2,%3}, {%4,%5,%6,%7}, {%8,%9}, {%0,%1,%2,%3};"
        : "+f"(d[0]), "+f"(d[1]), "+f"(d[2]), "+f"(d[3])
        : "r"(a[0]), "r"(a[1]), "r"(a[2]), "r"(a[3]), "r"(b0), "r"(b1));
}
__device__ __forceinline__ uint32_t smem_to_u32(const void* p) {
    uint32_t a;
    asm("{ .reg .u64 t; cvta.to.shared.u64 t, %1; cvt.u32.u64 %0, t; }"
        : "=r"(a) : "l"(p));
    return a;
}
__device__ __forceinline__ void cp16(uint32_t dst, const void* src) {
    size_t g = __cvta_generic_to_global(src);
    asm volatile("cp.async.cg.shared.global [%0], [%1], 16;"
                 :: "r"(dst), "l"(g) : "memory");
}
#define CP_COMMIT() asm volatile("cp.async.commit_group;" ::: "memory")
#define CP_WAIT0()  asm volatile("cp.async.wait_group 0;" ::: "memory")

// Scratch
__device__ uint32_t g_X[3 * SS * DD];     // tf32-rounded q,k,v
__device__ uint32_t g_Q[HH * SS * DHH];   // tf32, pre-scaled by SCALE_L2E
__device__ uint32_t g_K[HH * SS * DHH];   // tf32
__device__ uint32_t g_V[HH * SS * DHH];   // tf32
__device__ uint32_t g_O[HH * SS * DHH];   // tf32
__device__ uint32_t g_WT[64 * 64 * 1024]; // tf32, transposed weights

// ---------------------------------------------------------------------------
// Pre-convert q,k,v to tf32 bits
// ---------------------------------------------------------------------------
__global__ __launch_bounds__(256) void preconv(
    const float* __restrict__ q, const float* __restrict__ k,
    const float* __restrict__ v)
{
    const int n4 = SS * DD / 4;   // float4s per tensor
    for (int idx = blockIdx.x * 256 + threadIdx.x; idx < 3 * n4;
         idx += gridDim.x * 256) {
        int which = idx / n4, off = idx - which * n4;
        const float* src = (which == 0) ? q : (which == 1) ? k : v;
        float4 vv = *(const float4*)(src + (size_t)off * 4);
        uint4 u;
        u.x = f2tf(vv.x); u.y = f2tf(vv.y); u.z = f2tf(vv.z); u.w = f2tf(vv.w);
        *(uint4*)(g_X + (size_t)idx * 4) = u;
    }
}

// ---------------------------------------------------------------------------
// Weight pre-transpose: W[d][e] -> g_WT[slab][e][d] (tf32 bits)
// ---------------------------------------------------------------------------
__global__ __launch_bounds__(256) void transpose_w(
    const float* __restrict__ Wq, const float* __restrict__ Wk,
    const float* __restrict__ Wv, const float* __restrict__ Wo)
{
    __shared__ float tile[32][33];
    const int slab = blockIdx.z, which = slab >> 4, hh = slab & 15;
    const float* src; int ld; size_t off;
    if (which == 0)      { src = Wq; ld = DHH; off = (size_t)hh * DD * DHH; }
    else if (which == 1) { src = Wk; ld = DHH; off = (size_t)hh * DD * DHH; }
    else if (which == 2) { src = Wv; ld = DHH; off = (size_t)hh * DD * DHH; }
    else                 { src = Wo; ld = DD;  off = (size_t)hh * 64; }
    const int d0 = blockIdx.x * 32, e0 = blockIdx.y * 32;
    const int tx = threadIdx.x, ty = threadIdx.y;
    #pragma unroll
    for (int j = 0; j < 32; j += 8)
        tile[ty + j][tx] = src[off + (size_t)(d0 + ty + j) * ld + e0 + tx];
    __syncthreads();
    uint32_t* dst = g_WT + (size_t)slab * 65536;
    #pragma unroll
    for (int j = 0; j < 32; j += 8)
        dst[(size_t)(e0 + ty + j) * 1024 + d0 + tx] = f2tf(tile[tx][ty + j]);
}

// ---------------------------------------------------------------------------
// QKV projection, cp.async double-buffered.
// smem (words): As0[128*68] | As1 | Ws0[64*68] | Ws1
// ---------------------------------------------------------------------------
#define PROJ_SMEM ((2 * 128 * 68 + 2 * 64 * 68) * 4)

__global__ __launch_bounds__(256, 1) void proj_mma_kernel(
    const float* __restrict__ bq, const float* __restrict__ bk,
    const float* __restrict__ bv)
{
    extern __shared__ uint32_t sm[];
    const uint32_t sb = smem_to_u32(sm);
    const uint32_t asw[2] = { sb, sb + 128 * 68 * 4 };
    const uint32_t wsw[2] = { sb + 2 * 128 * 68 * 4,
                              sb + (2 * 128 * 68 + 64 * 68) * 4 };
    uint32_t* Asb[2] = { sm, sm + 128 * 68 };
    uint32_t* Wsb[2] = { sm + 2 * 128 * 68, sm + 2 * 128 * 68 + 64 * 68 };

    const int z  = blockIdx.z;
    const int h  = blockIdx.y;
    const int m0 = blockIdx.x * 128;
    const uint32_t* A  = g_X + (size_t)z * SS * DD;
    const float* biasp = ((z == 0) ? bq : (z == 1) ? bk : bv) + h * DHH;
    uint32_t* out = ((z == 0) ? g_Q : (z == 1) ? g_K : g_V)
                    + (size_t)h * SS * DHH;
    const uint32_t* WT = g_WT + (size_t)(z * 16 + h) * 65536;
    const float qscale = (z == 0) ? SCALE_L2E : 1.0f;

    const int t = threadIdx.x, wid = t >> 5, lane = t & 31;
    const int m0w = (wid >> 1) * 32, n0w = (wid & 1) * 32;
    const int lq = lane >> 2, ll = lane & 3;

    auto issue_chunk = [&](int kc, int buf) {
        const int k0 = kc * 64;
        #pragma unroll
        for (int it = 0; it < 8; it++) {
            int idx = t + it * 256;
            int r = idx >> 4, c4 = (idx & 15) * 4;
            cp16(asw[buf] + (r * 68 + c4) * 4,
                 A + (size_t)(m0 + r) * DD + k0 + c4);
        }
        #pragma unroll
        for (int it = 0; it < 4; it++) {
            int idx = t + it * 256;
            int e = idx >> 4, k4 = (idx & 15) * 4;
            cp16(wsw[buf] + (e * 68 + k4) * 4,
                 WT + (size_t)e * 1024 + k0 + k4);
        }
        CP_COMMIT();
    };

    float c[2][4][4] = {};
    issue_chunk(0, 0);

    for (int kc = 0; kc < 16; kc++) {
        const int cur = kc & 1;
        CP_WAIT0();
        __syncthreads();
        if (kc < 15) issue_chunk(kc + 1, cur ^ 1);

        uint32_t* As = Asb[cur];
        uint32_t* Ws = Wsb[cur];
        #pragma unroll
        for (int ks = 0; ks < 8; ks++) {
            uint32_t a[2][4];
            #pragma unroll
            for (int mt = 0; mt < 2; mt++) {
                int row = m0w + mt * 16 + lq, col = ks * 8 + ll;
                a[mt][0] = As[row * 68 + col];
                a[mt][1] = As[(row + 8) * 68 + col];
                a[mt][2] = As[row * 68 + col + 4];
                a[mt][3] = As[(row + 8) * 68 + col + 4];
            }
            #pragma unroll
            for (int nt = 0; nt < 4; nt++) {
                int nrow = n0w + nt * 8 + lq, col = ks * 8 + ll;
                uint32_t b0 = Ws[nrow * 68 + col];
                uint32_t b1 = Ws[nrow * 68 + col + 4];
                mma_tf32(c[0][nt], a[0], b0, b1);
                mma_tf32(c[1][nt], a[1], b0, b1);
            }
        }
    }

    #pragma unroll
    for (int mt = 0; mt < 2; mt++) {
        int row = m0w + mt * 16 + lq;
        #pragma unroll
        for (int nt = 0; nt < 4; nt++) {
            int col = n0w + nt * 8 + 2 * ll;
            uint2 o0, o1;
            o0.x = f2tf((c[mt][nt][0] + biasp[col]) * qscale);
            o0.y = f2tf((c[mt][nt][1] + biasp[col + 1]) * qscale);
            o1.x = f2tf((c[mt][nt][2] + biasp[col]) * qscale);
            o1.y = f2tf((c[mt][nt][3] + biasp[col + 1]) * qscale);
            *(uint2*)(out + (size_t)(m0 + row) * DHH + col) = o0;
            *(uint2*)(out + (size_t)(m0 + row + 8) * DHH + col) = o1;
        }
    }
}

// ---------------------------------------------------------------------------
// Output projection, cp.async double-buffered. Chunk kc == head.
// ---------------------------------------------------------------------------
__global__ __launch_bounds__(256, 1) void outproj_mma_kernel(
    const float* __restrict__ bo, float* __restrict__ Cout)
{
    extern __shared__ uint32_t sm[];
    const uint32_t sb = smem_to_u32(sm);
    const uint32_t asw[2] = { sb, sb + 128 * 68 * 4 };
    const uint32_t wsw[2] = { sb + 2 * 128 * 68 * 4,
                              sb + (2 * 128 * 68 + 64 * 68) * 4 };
    uint32_t* Asb[2] = { sm, sm + 128 * 68 };
    uint32_t* Wsb[2] = { sm + 2 * 128 * 68, sm + 2 * 128 * 68 + 64 * 68 };

    const int m0 = blockIdx.x * 128;
    const int n0 = blockIdx.y * 64;
    const uint32_t* WT = g_WT + (size_t)(48 + blockIdx.y) * 65536;
    const float* biasp = bo + n0;

    const int t = threadIdx.x, wid = t >> 5, lane = t & 31;
    const int m0w = (wid >> 1) * 32, n0w = (wid & 1) * 32;
    const int lq = lane >> 2, ll = lane & 3;

    auto issue_chunk = [&](int kc, int buf) {
        const int k0 = kc * 64;
        const uint32_t* A = g_O + (size_t)kc * SS * DHH;
        #pragma unroll
        for (int it = 0; it < 8; it++) {
            int idx = t + it * 256;
            int r = idx >> 4, c4 = (idx & 15) * 4;
            cp16(asw[buf] + (r * 68 + c4) * 4,
                 A + (size_t)(m0 + r) * DHH + c4);
        }
        #pragma unroll
        for (int it = 0; it < 4; it++) {
            int idx = t + it * 256;
            int e = idx >> 4, k4 = (idx & 15) * 4;
            cp16(wsw[buf] + (e * 68 + k4) * 4,
                 WT + (size_t)e * 1024 + k0 + k4);
        }
        CP_COMMIT();
    };

    float c[2][4][4] = {};
    issue_chunk(0, 0);

    for (int kc = 0; kc < 16; kc++) {
        const int cur = kc & 1;
        CP_WAIT0();
        __syncthreads();
        if (kc < 15) issue_chunk(kc + 1, cur ^ 1);

        uint32_t* As = Asb[cur];
        uint32_t* Ws = Wsb[cur];
        #pragma unroll
        for (int ks = 0; ks < 8; ks++) {
            uint32_t a[2][4];
            #pragma unroll
            for (int mt = 0; mt < 2; mt++) {
                int row = m0w + mt * 16 + lq, col = ks * 8 + ll;
                a[mt][0] = As[row * 68 + col];
                a[mt][1] = As[(row + 8) * 68 + col];
                a[mt][2] = As[row * 68 + col + 4];
                a[mt][3] = As[(row + 8) * 68 + col + 4];
            }
            #pragma unroll
            for (int nt = 0; nt < 4; nt++) {
                int nrow = n0w + nt * 8 + lq, col = ks * 8 + ll;
                uint32_t b0 = Ws[nrow * 68 + col];
                uint32_t b1 = Ws[nrow * 68 + col + 4];
                mma_tf32(c[0][nt], a[0], b0, b1);
                mma_tf32(c[1][nt], a[1], b0, b1);
            }
        }
    }

    #pragma unroll
    for (int mt = 0; mt < 2; mt++) {
        int row = m0w + mt * 16 + lq;
        #pragma unroll
        for (int nt = 0; nt < 4; nt++) {
            int col = n0w + nt * 8 + 2 * ll;
            float2 o0 = make_float2(c[mt][nt][0] + biasp[col],
                                    c[mt][nt][1] + biasp[col + 1]);
            float2 o1 = make_float2(c[mt][nt][2] + biasp[col],
                                    c[mt][nt][3] + biasp[col + 1]);
            *(float2*)(Cout + (size_t)(m0 + row) * DD + n0 + col) = o0;
            *(float2*)(Cout + (size_t)(m0 + row + 8) * DD + n0 + col) = o1;
        }
    }
}

// ---------------------------------------------------------------------------
// Flash attention, mma.sync tf32, cp.async double-buffered K/V (pure copies;
// g_Q/g_K/g_V already tf32, Q pre-scaled by log2e/32). P = ex2(S).
// smem (words): Qs[8704] | Ks0[8704] | Ks1[8704] | Vs0[9216] | Vs1[9216]
// Epilogue reuse: lred @0, Opart @8704.
// ---------------------------------------------------------------------------
#define ATTN_SMEM ((8704 * 3 + 9216 * 2) * 4)

__global__ __launch_bounds__(256, 1) void attn_kernel()
{
    extern __shared__ uint32_t smu[];
    const uint32_t sb = smem_to_u32(smu);
    uint32_t* Qs = smu;
    uint32_t* Ksb[2] = { smu + 8704, smu + 17408 };
    uint32_t* Vsb[2] = { smu + 26112, smu + 35328 };
    const uint32_t ksw[2] = { sb + 8704 * 4, sb + 17408 * 4 };
    const uint32_t vsw[2] = { sb + 26112 * 4, sb + 35328 * 4 };
    float* lred  = (float*)smu;            // [2][128]
    float* Opart = (float*)(smu + 8704);   // [128][68]

    const int t      = threadIdx.x;
    const int wid    = t >> 5;
    const int lane   = t & 31;
    const int warp_n = wid & 1;
    const int m0w    = (wid >> 1) * 32;
    const int n0w    = warp_n * 64;
    const int lq     = lane >> 2;
    const int ll     = lane & 3;

    const int m0 = blockIdx.x * 128;
    const int h  = blockIdx.y;
    const uint32_t* Qg = g_Q + (size_t)h * SS * DHH;
    const uint32_t* Kg = g_K + (size_t)h * SS * DHH;
    const uint32_t* Vg = g_V + (size_t)h * SS * DHH;

    auto issue_kv = [&](int kb0, int buf) {
        #pragma unroll
        for (int it = 0; it < 8; it++) {
            int idx = t + it * 256;
            int r = idx >> 4, c4 = (idx & 15) * 4;
            cp16(ksw[buf] + (r * 68 + c4) * 4,
                 Kg + (size_t)(kb0 + r) * DHH + c4);
        }
        #pragma unroll
        for (int it = 0; it < 8; it++) {
            int idx = t + it * 256;
            int kk = idx >> 4, e4 = (idx & 15) * 4;
            int pos = (kk & 0x78) | (((kk & 7) >> 1) + ((kk & 1) << 2));
            cp16(vsw[buf] + (pos * 72 + e4) * 4,
                 Vg + (size_t)(kb0 + kk) * DHH + e4);
        }
        CP_COMMIT();
    };

    // Q fill (pure copy) + first K/V tile, one group
    #pragma unroll
    for (int it = 0; it < 8; it++) {
        int idx = t + it * 256;
        int r = idx >> 4, c4 = (idx & 15) * 4;
        cp16(sb + (r * 68 + c4) * 4, Qg + (size_t)(m0 + r) * DHH + c4);
    }
    issue_kv(0, 0);

    float oC[2][8][4];
    #pragma unroll
    for (int mt = 0; mt < 2; mt++)
        #pragma unroll
        for (int nt = 0; nt < 8; nt++)
            #pragma unroll
            for (int i = 0; i < 4; i++) oC[mt][nt][i] = 0.0f;
    float lacc[2][2] = {};

    for (int kt = 0; kt < 32; kt++) {
        const int cur = kt & 1;
        CP_WAIT0();
        __syncthreads();
        if (kt < 31) issue_kv((kt + 1) * 128, cur ^ 1);

        uint32_t* Ks = Ksb[cur];
        uint32_t* Vs = Vsb[cur];

        float sC[2][8][4];
        #pragma unroll
        for (int mt = 0; mt < 2; mt++)
            #pragma unroll
            for (int nt = 0; nt < 8; nt++)
                #pragma unroll
                for (int i = 0; i < 4; i++) sC[mt][nt][i] = 0.0f;

        #pragma unroll
        for (int ks = 0; ks < 8; ks++) {
            uint32_t a[2][4];
            #pragma unroll
            for (int mt = 0; mt < 2; mt++) {
                int row = m0w + mt * 16 + lq;
                int col = ks * 8 + ll;
                a[mt][0] = Qs[row * 68 + col];
                a[mt][1] = Qs[(row + 8) * 68 + col];
                a[mt][2] = Qs[row * 68 + col + 4];
                a[mt][3] = Qs[(row + 8) * 68 + col + 4];
            }
            #pragma unroll
            for (int nt = 0; nt < 8; nt++) {
                int krow = n0w + nt * 8 + lq;
                int kcol = ks * 8 + ll;
                uint32_t b0 = Ks[krow * 68 + kcol];
                uint32_t b1 = Ks[krow * 68 + kcol + 4];
                mma_tf32(sC[0][nt], a[0], b0, b1);
                mma_tf32(sC[1][nt], a[1], b0, b1);
            }
        }

        // P = 2^S, accumulate row sums
        #pragma unroll
        for (int mt = 0; mt < 2; mt++)
            #pragma unroll
            for (int nt = 0; nt < 8; nt++)
                #pragma unroll
                for (int i = 0; i < 4; i++) {
                    float p = ex2f(sC[mt][nt][i]);
                    lacc[mt][i >> 1] += p;
                    sC[mt][nt][i] = __uint_as_float(f2tf(p));
                }

        // O += P V
        #pragma unroll
        for (int ks = 0; ks < 8; ks++) {
            uint32_t A0[4] = { __float_as_uint(sC[0][ks][0]),
                               __float_as_uint(sC[0][ks][2]),
                               __float_as_uint(sC[0][ks][1]),
                               __float_as_uint(sC[0][ks][3]) };
            uint32_t A1[4] = { __float_as_uint(sC[1][ks][0]),
                               __float_as_uint(sC[1][ks][2]),
                               __float_as_uint(sC[1][ks][1]),
                               __float_as_uint(sC[1][ks][3]) };
            int posb = n0w + ks * 8 + ll;
            #pragma unroll
            for (int nt2 = 0; nt2 < 8; nt2++) {
                int e = nt2 * 8 + lq;
                uint32_t b0 = Vs[posb * 72 + e];
                uint32_t b1 = Vs[(posb + 4) * 72 + e];
                mma_tf32(oC[0][nt2], A0, b0, b1);
                mma_tf32(oC[1][nt2], A1, b0, b1);
            }
        }
    }

    __syncthreads();   // compute done; reuse Qs/Ks0 smem

    #pragma unroll
    for (int mt = 0; mt < 2; mt++)
        #pragma unroll
        for (int half = 0; half < 2; half++) {
            float ls = lacc[mt][half];
            ls += __shfl_xor_sync(0xffffffffu, ls, 1);
            ls += __shfl_xor_sync(0xffffffffu, ls, 2);
            if (ll == 0) {
                int row = m0w + mt * 16 + half * 8 + lq;
                lred[warp_n * 128 + row] = ls;
            }
        }
    if (warp_n == 1) {
        #pragma unroll
        for (int mt = 0; mt < 2; mt++)
            #pragma unroll
            for (int nt2 = 0; nt2 < 8; nt2++) {
                int row = m0w + mt * 16 + lq;
                int col = nt2 * 8 + 2 * ll;
                *(float2*)(Opart + row * 68 + col) =
                    make_float2(oC[mt][nt2][0], oC[mt][nt2][1]);
                *(float2*)(Opart + (row + 8) * 68 + col) =
                    make_float2(oC[mt][nt2][2], oC[mt][nt2][3]);
            }
    }
    __syncthreads();

    if (warp_n == 0) {
        uint32_t* Og = g_O + (size_t)h * SS * DHH;
        #pragma unroll
        for (int mt = 0; mt < 2; mt++) {
            int row = m0w + mt * 16 + lq;
            float li0 = 1.0f / (lred[row] + lred[128 + row]);
            float li1 = 1.0f / (lred[row + 8] + lred[128 + row + 8]);
            #pragma unroll
            for (int nt2 = 0; nt2 < 8; nt2++) {
                int col = nt2 * 8 + 2 * ll;
                float2 p0 = *(float2*)(Opart + row * 68 + col);
                float2 p1 = *(float2*)(Opart + (row + 8) * 68 + col);
                uint2 o0, o1;
                o0.x = f2tf((oC[mt][nt2][0] + p0.x) * li0);
                o0.y = f2tf((oC[mt][nt2][1] + p0.y) * li0);
                o1.x = f2tf((oC[mt][nt2][2] + p1.x) * li1);
                o1.y = f2tf((oC[mt][nt2][3] + p1.y) * li1);
                *(uint2*)(Og + (size_t)(m0 + row) * DHH + col) = o0;
                *(uint2*)(Og + (size_t)(m0 + row + 8) * DHH + col) = o1;
            }
        }
    }
}

// ---------------------------------------------------------------------------
extern "C" void kernel_launch(void* const* d_in, const int* in_sizes, int n_in,
                              void* d_out, int out_size)
{
    const float* q  = (const float*)d_in[0];
    const float* k  = (const float*)d_in[1];
    const float* v  = (const float*)d_in[2];
    const float* Wq = (const float*)d_in[3];
    const float* bq = (const float*)d_in[4];
    const float* Wk = (const float*)d_in[5];
    const float* bk = (const float*)d_in[6];
    const float* Wv = (const float*)d_in[7];
    const float* bv = (const float*)d_in[8];
    const float* Wo = (const float*)d_in[9];
    const float* bo = (const float*)d_in[10];
    float* out = (float*)d_out;

    preconv<<<1024, 256>>>(q, k, v);
    transpose_w<<<dim3(32, 2, 64), dim3(32, 8)>>>(Wq, Wk, Wv, Wo);

    cudaFuncSetAttribute(proj_mma_kernel,
                         cudaFuncAttributeMaxDynamicSharedMemorySize, PROJ_SMEM);
    proj_mma_kernel<<<dim3(SS / 128, HH, 3), 256, PROJ_SMEM>>>(bq, bk, bv);

    cudaFuncSetAttribute(attn_kernel,
                         cudaFuncAttributeMaxDynamicSharedMemorySize, ATTN_SMEM);
    attn_kernel<<<dim3(SS / 128, HH), 256, ATTN_SMEM>>>();

    cudaFuncSetAttribute(outproj_mma_kernel,
                         cudaFuncAttributeMaxDynamicSharedMemorySize, PROJ_SMEM);
    outproj_mma_kernel<<<dim3(SS / 128, DD / 64), 256, PROJ_SMEM>>>(bo, out);
}

// round 8
// speedup vs baseline: 1.7876x; 1.1236x over previous
#include <cuda_runtime.h>
#include <cstdint>

#define SS 4096
#define DD 1024
#define HH 16
#define DHH 64
#define SCALE_L2E 0.045111762f             // (1/32) * log2(e)

__device__ __forceinline__ uint32_t f2tf(float f) {
    uint32_t r; asm("cvt.rna.tf32.f32 %0, %1;" : "=r"(r) : "f"(f)); return r;
}
__device__ __forceinline__ float ex2f(float x) {
    float r; asm("ex2.approx.f32 %0, %1;" : "=f"(r) : "f"(x)); return r;
}
__device__ __forceinline__ void mma_tf32(float* d, const uint32_t* a,
                                         uint32_t b0, uint32_t b1) {
    asm volatile(
        "mma.sync.aligned.m16n8k8.row.col.f32.tf32.tf32.f32 "
        "{%0,%1,%2,%3}, {%4,%5,%6,%7}, {%8,%9}, {%0,%1,%2,%3};"
        : "+f"(d[0]), "+f"(d[1]), "+f"(d[2]), "+f"(d[3])
        : "r"(a[0]), "r"(a[1]), "r"(a[2]), "r"(a[3]), "r"(b0), "r"(b1));
}
__device__ __forceinline__ uint32_t smem_to_u32(const void* p) {
    uint32_t a;
    asm("{ .reg .u64 t; cvta.to.shared.u64 t, %1; cvt.u32.u64 %0, t; }"
        : "=r"(a) : "l"(p));
    return a;
}
__device__ __forceinline__ void cp16(uint32_t dst, const void* src) {
    size_t g = __cvta_generic_to_global(src);
    asm volatile("cp.async.cg.shared.global [%0], [%1], 16;"
                 :: "r"(dst), "l"(g) : "memory");
}
#define CP_COMMIT() asm volatile("cp.async.commit_group;" ::: "memory")
#define CP_WAIT0()  asm volatile("cp.async.wait_group 0;" ::: "memory")

// Scratch
__device__ uint32_t g_X[3 * SS * DD];     // tf32-rounded q,k,v
__device__ uint32_t g_Q[HH * SS * DHH];   // tf32, pre-scaled by SCALE_L2E
__device__ uint32_t g_K[HH * SS * DHH];   // tf32
__device__ uint32_t g_V[HH * SS * DHH];   // tf32
__device__ uint32_t g_O[HH * SS * DHH];   // tf32
__device__ uint32_t g_WT[64 * 64 * 1024]; // tf32, transposed weights

// ---------------------------------------------------------------------------
// Pre-convert q,k,v to tf32 bits
// ---------------------------------------------------------------------------
__global__ __launch_bounds__(256) void preconv(
    const float* __restrict__ q, const float* __restrict__ k,
    const float* __restrict__ v)
{
    const int n4 = SS * DD / 4;
    for (int idx = blockIdx.x * 256 + threadIdx.x; idx < 3 * n4;
         idx += gridDim.x * 256) {
        int which = idx / n4, off = idx - which * n4;
        const float* src = (which == 0) ? q : (which == 1) ? k : v;
        float4 vv = *(const float4*)(src + (size_t)off * 4);
        uint4 u;
        u.x = f2tf(vv.x); u.y = f2tf(vv.y); u.z = f2tf(vv.z); u.w = f2tf(vv.w);
        *(uint4*)(g_X + (size_t)idx * 4) = u;
    }
}

// ---------------------------------------------------------------------------
// Weight pre-transpose: W[d][e] -> g_WT[slab][e][d] (tf32 bits)
// ---------------------------------------------------------------------------
__global__ __launch_bounds__(256) void transpose_w(
    const float* __restrict__ Wq, const float* __restrict__ Wk,
    const float* __restrict__ Wv, const float* __restrict__ Wo)
{
    __shared__ float tile[32][33];
    const int slab = blockIdx.z, which = slab >> 4, hh = slab & 15;
    const float* src; int ld; size_t off;
    if (which == 0)      { src = Wq; ld = DHH; off = (size_t)hh * DD * DHH; }
    else if (which == 1) { src = Wk; ld = DHH; off = (size_t)hh * DD * DHH; }
    else if (which == 2) { src = Wv; ld = DHH; off = (size_t)hh * DD * DHH; }
    else                 { src = Wo; ld = DD;  off = (size_t)hh * 64; }
    const int d0 = blockIdx.x * 32, e0 = blockIdx.y * 32;
    const int tx = threadIdx.x, ty = threadIdx.y;
    #pragma unroll
    for (int j = 0; j < 32; j += 8)
        tile[ty + j][tx] = src[off + (size_t)(d0 + ty + j) * ld + e0 + tx];
    __syncthreads();
    uint32_t* dst = g_WT + (size_t)slab * 65536;
    #pragma unroll
    for (int j = 0; j < 32; j += 8)
        dst[(size_t)(e0 + ty + j) * 1024 + d0 + tx] = f2tf(tile[tx][ty + j]);
}

// ---------------------------------------------------------------------------
// QKV projection, single-buffered (51 KB -> 2 CTAs/SM), pure uint4 fills.
// smem (words): As[128*68] | Ws[64*68]
// ---------------------------------------------------------------------------
#define PROJ_SMEM ((128 * 68 + 64 * 68) * 4)

__global__ __launch_bounds__(256, 1) void proj_mma_kernel(
    const float* __restrict__ bq, const float* __restrict__ bk,
    const float* __restrict__ bv)
{
    extern __shared__ uint32_t sm[];
    uint32_t* As = sm;             // [128][68]
    uint32_t* Ws = sm + 128 * 68;  // [64][68]

    const int z  = blockIdx.z;
    const int h  = blockIdx.y;
    const int m0 = blockIdx.x * 128;
    const uint32_t* A  = g_X + (size_t)z * SS * DD;
    const float* biasp = ((z == 0) ? bq : (z == 1) ? bk : bv) + h * DHH;
    uint32_t* out = ((z == 0) ? g_Q : (z == 1) ? g_K : g_V)
                    + (size_t)h * SS * DHH;
    const uint32_t* WT = g_WT + (size_t)(z * 16 + h) * 65536;
    const float qscale = (z == 0) ? SCALE_L2E : 1.0f;

    const int t = threadIdx.x, wid = t >> 5, lane = t & 31;
    const int m0w = (wid >> 1) * 32, n0w = (wid & 1) * 32;
    const int lq = lane >> 2, ll = lane & 3;

    float c[2][4][4] = {};

    for (int kc = 0; kc < 16; kc++) {
        const int k0 = kc * 64;
        __syncthreads();
        #pragma unroll
        for (int it = 0; it < 8; it++) {
            int idx = t + it * 256;
            int r = idx >> 4, c4 = (idx & 15) * 4;
            *(uint4*)(As + r * 68 + c4) =
                *(const uint4*)(A + (size_t)(m0 + r) * DD + k0 + c4);
        }
        #pragma unroll
        for (int it = 0; it < 4; it++) {
            int idx = t + it * 256;
            int e = idx >> 4, k4 = (idx & 15) * 4;
            *(uint4*)(Ws + e * 68 + k4) =
                *(const uint4*)(WT + (size_t)e * 1024 + k0 + k4);
        }
        __syncthreads();

        #pragma unroll
        for (int ks = 0; ks < 8; ks++) {
            uint32_t a[2][4];
            #pragma unroll
            for (int mt = 0; mt < 2; mt++) {
                int row = m0w + mt * 16 + lq, col = ks * 8 + ll;
                a[mt][0] = As[row * 68 + col];
                a[mt][1] = As[(row + 8) * 68 + col];
                a[mt][2] = As[row * 68 + col + 4];
                a[mt][3] = As[(row + 8) * 68 + col + 4];
            }
            #pragma unroll
            for (int nt = 0; nt < 4; nt++) {
                int nrow = n0w + nt * 8 + lq, col = ks * 8 + ll;
                uint32_t b0 = Ws[nrow * 68 + col];
                uint32_t b1 = Ws[nrow * 68 + col + 4];
                mma_tf32(c[0][nt], a[0], b0, b1);
                mma_tf32(c[1][nt], a[1], b0, b1);
            }
        }
    }

    #pragma unroll
    for (int mt = 0; mt < 2; mt++) {
        int row = m0w + mt * 16 + lq;
        #pragma unroll
        for (int nt = 0; nt < 4; nt++) {
            int col = n0w + nt * 8 + 2 * ll;
            uint2 o0, o1;
            o0.x = f2tf((c[mt][nt][0] + biasp[col]) * qscale);
            o0.y = f2tf((c[mt][nt][1] + biasp[col + 1]) * qscale);
            o1.x = f2tf((c[mt][nt][2] + biasp[col]) * qscale);
            o1.y = f2tf((c[mt][nt][3] + biasp[col + 1]) * qscale);
            *(uint2*)(out + (size_t)(m0 + row) * DHH + col) = o0;
            *(uint2*)(out + (size_t)(m0 + row + 8) * DHH + col) = o1;
        }
    }
}

// ---------------------------------------------------------------------------
// Output projection, single-buffered, pure uint4 fills. Chunk kc == head.
// ---------------------------------------------------------------------------
__global__ __launch_bounds__(256, 1) void outproj_mma_kernel(
    const float* __restrict__ bo, float* __restrict__ Cout)
{
    extern __shared__ uint32_t sm[];
    uint32_t* As = sm;
    uint32_t* Ws = sm + 128 * 68;

    const int m0 = blockIdx.x * 128;
    const int n0 = blockIdx.y * 64;
    const uint32_t* WT = g_WT + (size_t)(48 + blockIdx.y) * 65536;
    const float* biasp = bo + n0;

    const int t = threadIdx.x, wid = t >> 5, lane = t & 31;
    const int m0w = (wid >> 1) * 32, n0w = (wid & 1) * 32;
    const int lq = lane >> 2, ll = lane & 3;

    float c[2][4][4] = {};

    for (int kc = 0; kc < 16; kc++) {
        const int k0 = kc * 64;
        const uint32_t* A = g_O + (size_t)kc * SS * DHH;
        __syncthreads();
        #pragma unroll
        for (int it = 0; it < 8; it++) {
            int idx = t + it * 256;
            int r = idx >> 4, c4 = (idx & 15) * 4;
            *(uint4*)(As + r * 68 + c4) =
                *(const uint4*)(A + (size_t)(m0 + r) * DHH + c4);
        }
        #pragma unroll
        for (int it = 0; it < 4; it++) {
            int idx = t + it * 256;
            int e = idx >> 4, k4 = (idx & 15) * 4;
            *(uint4*)(Ws + e * 68 + k4) =
                *(const uint4*)(WT + (size_t)e * 1024 + k0 + k4);
        }
        __syncthreads();

        #pragma unroll
        for (int ks = 0; ks < 8; ks++) {
            uint32_t a[2][4];
            #pragma unroll
            for (int mt = 0; mt < 2; mt++) {
                int row = m0w + mt * 16 + lq, col = ks * 8 + ll;
                a[mt][0] = As[row * 68 + col];
                a[mt][1] = As[(row + 8) * 68 + col];
                a[mt][2] = As[row * 68 + col + 4];
                a[mt][3] = As[(row + 8) * 68 + col + 4];
            }
            #pragma unroll
            for (int nt = 0; nt < 4; nt++) {
                int nrow = n0w + nt * 8 + lq, col = ks * 8 + ll;
                uint32_t b0 = Ws[nrow * 68 + col];
                uint32_t b1 = Ws[nrow * 68 + col + 4];
                mma_tf32(c[0][nt], a[0], b0, b1);
                mma_tf32(c[1][nt], a[1], b0, b1);
            }
        }
    }

    #pragma unroll
    for (int mt = 0; mt < 2; mt++) {
        int row = m0w + mt * 16 + lq;
        #pragma unroll
        for (int nt = 0; nt < 4; nt++) {
            int col = n0w + nt * 8 + 2 * ll;
            float2 o0 = make_float2(c[mt][nt][0] + biasp[col],
                                    c[mt][nt][1] + biasp[col + 1]);
            float2 o1 = make_float2(c[mt][nt][2] + biasp[col],
                                    c[mt][nt][3] + biasp[col + 1]);
            *(float2*)(Cout + (size_t)(m0 + row) * DD + n0 + col) = o0;
            *(float2*)(Cout + (size_t)(m0 + row + 8) * DD + n0 + col) = o1;
        }
    }
}

// ---------------------------------------------------------------------------
// Flash attention (unchanged from R7: cp.async double-buffered, 483 us)
// ---------------------------------------------------------------------------
#define ATTN_SMEM ((8704 * 3 + 9216 * 2) * 4)

__global__ __launch_bounds__(256, 1) void attn_kernel()
{
    extern __shared__ uint32_t smu[];
    const uint32_t sb = smem_to_u32(smu);
    uint32_t* Qs = smu;
    uint32_t* Ksb[2] = { smu + 8704, smu + 17408 };
    uint32_t* Vsb[2] = { smu + 26112, smu + 35328 };
    const uint32_t ksw[2] = { sb + 8704 * 4, sb + 17408 * 4 };
    const uint32_t vsw[2] = { sb + 26112 * 4, sb + 35328 * 4 };
    float* lred  = (float*)smu;            // [2][128]
    float* Opart = (float*)(smu + 8704);   // [128][68]

    const int t      = threadIdx.x;
    const int wid    = t >> 5;
    const int lane   = t & 31;
    const int warp_n = wid & 1;
    const int m0w    = (wid >> 1) * 32;
    const int n0w    = warp_n * 64;
    const int lq     = lane >> 2;
    const int ll     = lane & 3;

    const int m0 = blockIdx.x * 128;
    const int h  = blockIdx.y;
    const uint32_t* Qg = g_Q + (size_t)h * SS * DHH;
    const uint32_t* Kg = g_K + (size_t)h * SS * DHH;
    const uint32_t* Vg = g_V + (size_t)h * SS * DHH;

    auto issue_kv = [&](int kb0, int buf) {
        #pragma unroll
        for (int it = 0; it < 8; it++) {
            int idx = t + it * 256;
            int r = idx >> 4, c4 = (idx & 15) * 4;
            cp16(ksw[buf] + (r * 68 + c4) * 4,
                 Kg + (size_t)(kb0 + r) * DHH + c4);
        }
        #pragma unroll
        for (int it = 0; it < 8; it++) {
            int idx = t + it * 256;
            int kk = idx >> 4, e4 = (idx & 15) * 4;
            int pos = (kk & 0x78) | (((kk & 7) >> 1) + ((kk & 1) << 2));
            cp16(vsw[buf] + (pos * 72 + e4) * 4,
                 Vg + (size_t)(kb0 + kk) * DHH + e4);
        }
        CP_COMMIT();
    };

    #pragma unroll
    for (int it = 0; it < 8; it++) {
        int idx = t + it * 256;
        int r = idx >> 4, c4 = (idx & 15) * 4;
        cp16(sb + (r * 68 + c4) * 4, Qg + (size_t)(m0 + r) * DHH + c4);
    }
    issue_kv(0, 0);

    float oC[2][8][4];
    #pragma unroll
    for (int mt = 0; mt < 2; mt++)
        #pragma unroll
        for (int nt = 0; nt < 8; nt++)
            #pragma unroll
            for (int i = 0; i < 4; i++) oC[mt][nt][i] = 0.0f;
    float lacc[2][2] = {};

    for (int kt = 0; kt < 32; kt++) {
        const int cur = kt & 1;
        CP_WAIT0();
        __syncthreads();
        if (kt < 31) issue_kv((kt + 1) * 128, cur ^ 1);

        uint32_t* Ks = Ksb[cur];
        uint32_t* Vs = Vsb[cur];

        float sC[2][8][4];
        #pragma unroll
        for (int mt = 0; mt < 2; mt++)
            #pragma unroll
            for (int nt = 0; nt < 8; nt++)
                #pragma unroll
                for (int i = 0; i < 4; i++) sC[mt][nt][i] = 0.0f;

        #pragma unroll
        for (int ks = 0; ks < 8; ks++) {
            uint32_t a[2][4];
            #pragma unroll
            for (int mt = 0; mt < 2; mt++) {
                int row = m0w + mt * 16 + lq;
                int col = ks * 8 + ll;
                a[mt][0] = Qs[row * 68 + col];
                a[mt][1] = Qs[(row + 8) * 68 + col];
                a[mt][2] = Qs[row * 68 + col + 4];
                a[mt][3] = Qs[(row + 8) * 68 + col + 4];
            }
            #pragma unroll
            for (int nt = 0; nt < 8; nt++) {
                int krow = n0w + nt * 8 + lq;
                int kcol = ks * 8 + ll;
                uint32_t b0 = Ks[krow * 68 + kcol];
                uint32_t b1 = Ks[krow * 68 + kcol + 4];
                mma_tf32(sC[0][nt], a[0], b0, b1);
                mma_tf32(sC[1][nt], a[1], b0, b1);
            }
        }

        #pragma unroll
        for (int mt = 0; mt < 2; mt++)
            #pragma unroll
            for (int nt = 0; nt < 8; nt++)
                #pragma unroll
                for (int i = 0; i < 4; i++) {
                    float p = ex2f(sC[mt][nt][i]);
                    lacc[mt][i >> 1] += p;
                    sC[mt][nt][i] = __uint_as_float(f2tf(p));
                }

        #pragma unroll
        for (int ks = 0; ks < 8; ks++) {
            uint32_t A0[4] = { __float_as_uint(sC[0][ks][0]),
                               __float_as_uint(sC[0][ks][2]),
                               __float_as_uint(sC[0][ks][1]),
                               __float_as_uint(sC[0][ks][3]) };
            uint32_t A1[4] = { __float_as_uint(sC[1][ks][0]),
                               __float_as_uint(sC[1][ks][2]),
                               __float_as_uint(sC[1][ks][1]),
                               __float_as_uint(sC[1][ks][3]) };
            int posb = n0w + ks * 8 + ll;
            #pragma unroll
            for (int nt2 = 0; nt2 < 8; nt2++) {
                int e = nt2 * 8 + lq;
                uint32_t b0 = Vs[posb * 72 + e];
                uint32_t b1 = Vs[(posb + 4) * 72 + e];
                mma_tf32(oC[0][nt2], A0, b0, b1);
                mma_tf32(oC[1][nt2], A1, b0, b1);
            }
        }
    }

    __syncthreads();

    #pragma unroll
    for (int mt = 0; mt < 2; mt++)
        #pragma unroll
        for (int half = 0; half < 2; half++) {
            float ls = lacc[mt][half];
            ls += __shfl_xor_sync(0xffffffffu, ls, 1);
            ls += __shfl_xor_sync(0xffffffffu, ls, 2);
            if (ll == 0) {
                int row = m0w + mt * 16 + half * 8 + lq;
                lred[warp_n * 128 + row] = ls;
            }
        }
    if (warp_n == 1) {
        #pragma unroll
        for (int mt = 0; mt < 2; mt++)
            #pragma unroll
            for (int nt2 = 0; nt2 < 8; nt2++) {
                int row = m0w + mt * 16 + lq;
                int col = nt2 * 8 + 2 * ll;
                *(float2*)(Opart + row * 68 + col) =
                    make_float2(oC[mt][nt2][0], oC[mt][nt2][1]);
                *(float2*)(Opart + (row + 8) * 68 + col) =
                    make_float2(oC[mt][nt2][2], oC[mt][nt2][3]);
            }
    }
    __syncthreads();

    if (warp_n == 0) {
        uint32_t* Og = g_O + (size_t)h * SS * DHH;
        #pragma unroll
        for (int mt = 0; mt < 2; mt++) {
            int row = m0w + mt * 16 + lq;
            float li0 = 1.0f / (lred[row] + lred[128 + row]);
            float li1 = 1.0f / (lred[row + 8] + lred[128 + row + 8]);
            #pragma unroll
            for (int nt2 = 0; nt2 < 8; nt2++) {
                int col = nt2 * 8 + 2 * ll;
                float2 p0 = *(float2*)(Opart + row * 68 + col);
                float2 p1 = *(float2*)(Opart + (row + 8) * 68 + col);
                uint2 o0, o1;
                o0.x = f2tf((oC[mt][nt2][0] + p0.x) * li0);
                o0.y = f2tf((oC[mt][nt2][1] + p0.y) * li0);
                o1.x = f2tf((oC[mt][nt2][2] + p1.x) * li1);
                o1.y = f2tf((oC[mt][nt2][3] + p1.y) * li1);
                *(uint2*)(Og + (size_t)(m0 + row) * DHH + col) = o0;
                *(uint2*)(Og + (size_t)(m0 + row + 8) * DHH + col) = o1;
            }
        }
    }
}

// ---------------------------------------------------------------------------
extern "C" void kernel_launch(void* const* d_in, const int* in_sizes, int n_in,
                              void* d_out, int out_size)
{
    const float* q  = (const float*)d_in[0];
    const float* k  = (const float*)d_in[1];
    const float* v  = (const float*)d_in[2];
    const float* Wq = (const float*)d_in[3];
    const float* bq = (const float*)d_in[4];
    const float* Wk = (const float*)d_in[5];
    const float* bk = (const float*)d_in[6];
    const float* Wv = (const float*)d_in[7];
    const float* bv = (const float*)d_in[8];
    const float* Wo = (const float*)d_in[9];
    const float* bo = (const float*)d_in[10];
    float* out = (float*)d_out;

    preconv<<<1024, 256>>>(q, k, v);
    transpose_w<<<dim3(32, 2, 64), dim3(32, 8)>>>(Wq, Wk, Wv, Wo);

    cudaFuncSetAttribute(proj_mma_kernel,
                         cudaFuncAttributeMaxDynamicSharedMemorySize, PROJ_SMEM);
    proj_mma_kernel<<<dim3(SS / 128, HH, 3), 256, PROJ_SMEM>>>(bq, bk, bv);

    cudaFuncSetAttribute(attn_kernel,
                         cudaFuncAttributeMaxDynamicSharedMemorySize, ATTN_SMEM);
    attn_kernel<<<dim3(SS / 128, HH), 256, ATTN_SMEM>>>();

    cudaFuncSetAttribute(outproj_mma_kernel,
                         cudaFuncAttributeMaxDynamicSharedMemorySize, PROJ_SMEM);
    outproj_mma_kernel<<<dim3(SS / 128, DD / 64), 256, PROJ_SMEM>>>(bo, out);
}

// round 9
// speedup vs baseline: 3.0866x; 1.7267x over previous
#include <cuda_runtime.h>
#include <cuda_fp16.h>
#include <cstdint>

#define SS 4096
#define DD 1024
#define HH 16
#define DHH 64
#define SCALE_L2E 0.045111762f             // (1/32) * log2(e)

__device__ __forceinline__ float ex2f(float x) {
    float r; asm("ex2.approx.f32 %0, %1;" : "=f"(r) : "f"(x)); return r;
}
// pack two f32 -> half2 (lo = first arg)
__device__ __forceinline__ uint32_t pkh2(float lo, float hi) {
    uint32_t r;
    asm("cvt.rn.f16x2.f32 %0, %1, %2;" : "=r"(r) : "f"(hi), "f"(lo));
    return r;
}
__device__ __forceinline__ void mma_f16(float* d, const uint32_t* a,
                                        uint32_t b0, uint32_t b1) {
    asm volatile(
        "mma.sync.aligned.m16n8k16.row.col.f32.f16.f16.f32 "
        "{%0,%1,%2,%3}, {%4,%5,%6,%7}, {%8,%9}, {%0,%1,%2,%3};"
        : "+f"(d[0]), "+f"(d[1]), "+f"(d[2]), "+f"(d[3])
        : "r"(a[0]), "r"(a[1]), "r"(a[2]), "r"(a[3]), "r"(b0), "r"(b1));
}
__device__ __forceinline__ uint32_t smem_to_u32(const void* p) {
    uint32_t a;
    asm("{ .reg .u64 t; cvta.to.shared.u64 t, %1; cvt.u32.u64 %0, t; }"
        : "=r"(a) : "l"(p));
    return a;
}
__device__ __forceinline__ void cp16(uint32_t dst, const void* src) {
    size_t g = __cvta_generic_to_global(src);
    asm volatile("cp.async.cg.shared.global [%0], [%1], 16;"
                 :: "r"(dst), "l"(g) : "memory");
}
#define CP_COMMIT() asm volatile("cp.async.commit_group;" ::: "memory")
#define CP_WAIT0()  asm volatile("cp.async.wait_group 0;" ::: "memory")

// Scratch (all fp16, stored as packed uint32 words = half2)
__device__ uint32_t g_X[3 * SS * DD / 2];     // q,k,v inputs [z][s][d]
__device__ uint32_t g_Q[HH * SS * DHH / 2];   // [h][s][e]  (unscaled)
__device__ uint32_t g_K[HH * SS * DHH / 2];   // [h][s][e]
__device__ uint32_t g_V[HH * SS * DHH / 2];   // [h][s/2][e][2] key-pair interleaved
__device__ uint32_t g_O[HH * SS * DHH / 2];   // [h][s][e]
__device__ uint32_t g_WT[64 * 64 * 1024 / 2]; // [slab][n][k] transposed weights

// ---------------------------------------------------------------------------
// Pre-convert q,k,v to fp16
// ---------------------------------------------------------------------------
__global__ __launch_bounds__(256) void preconv(
    const float* __restrict__ q, const float* __restrict__ k,
    const float* __restrict__ v)
{
    const int n4 = SS * DD / 4;
    for (int idx = blockIdx.x * 256 + threadIdx.x; idx < 3 * n4;
         idx += gridDim.x * 256) {
        int which = idx / n4, off = idx - which * n4;
        const float* src = (which == 0) ? q : (which == 1) ? k : v;
        float4 vv = *(const float4*)(src + (size_t)off * 4);
        uint2 u;
        u.x = pkh2(vv.x, vv.y);
        u.y = pkh2(vv.z, vv.w);
        *(uint2*)(g_X + (size_t)idx * 2) = u;
    }
}

// ---------------------------------------------------------------------------
// Weight pre-transpose: W[d][e] -> g_WT[slab][e][d] fp16
// ---------------------------------------------------------------------------
__global__ __launch_bounds__(256) void transpose_w(
    const float* __restrict__ Wq, const float* __restrict__ Wk,
    const float* __restrict__ Wv, const float* __restrict__ Wo)
{
    __shared__ float tile[32][33];
    const int slab = blockIdx.z, which = slab >> 4, hh = slab & 15;
    const float* src; int ld; size_t off;
    if (which == 0)      { src = Wq; ld = DHH; off = (size_t)hh * DD * DHH; }
    else if (which == 1) { src = Wk; ld = DHH; off = (size_t)hh * DD * DHH; }
    else if (which == 2) { src = Wv; ld = DHH; off = (size_t)hh * DD * DHH; }
    else                 { src = Wo; ld = DD;  off = (size_t)hh * 64; }
    const int d0 = blockIdx.x * 32, e0 = blockIdx.y * 32;
    const int tx = threadIdx.x, ty = threadIdx.y;
    #pragma unroll
    for (int j = 0; j < 32; j += 8)
        tile[ty + j][tx] = src[off + (size_t)(d0 + ty + j) * ld + e0 + tx];
    __syncthreads();
    __half* dst = (__half*)g_WT + (size_t)slab * 65536;
    #pragma unroll
    for (int j = 0; j < 32; j += 8)
        dst[(size_t)(e0 + ty + j) * 1024 + d0 + tx] =
            __float2half_rn(tile[tx][ty + j]);
}

// ---------------------------------------------------------------------------
// QKV projection, fp16 m16n8k16. CTA = (128 s-rows, head, which).
// smem (words): As[128*36] | Ws[64*36]  (row = 64 halves + pad, 144B)
// ---------------------------------------------------------------------------
#define PROJ_SMEM ((128 * 36 + 64 * 36) * 4)

__global__ __launch_bounds__(256, 1) void proj_mma_kernel(
    const float* __restrict__ bq, const float* __restrict__ bk,
    const float* __restrict__ bv)
{
    extern __shared__ uint32_t sm[];
    uint32_t* As = sm;            // [128][36]
    uint32_t* Ws = sm + 128 * 36; // [64][36]

    const int z  = blockIdx.z;
    const int h  = blockIdx.y;
    const int m0 = blockIdx.x * 128;
    const uint32_t* A  = g_X + (size_t)z * SS * DD / 2;
    const float* biasp = ((z == 0) ? bq : (z == 1) ? bk : bv) + h * DHH;
    uint32_t* out = ((z == 0) ? g_Q : (z == 1) ? g_K : g_V)
                    + (size_t)h * SS * DHH / 2;
    const uint32_t* WT = g_WT + (size_t)(z * 16 + h) * 32768;

    const int t = threadIdx.x, wid = t >> 5, lane = t & 31;
    const int m0w = (wid >> 1) * 32, n0w = (wid & 1) * 32;
    const int lq = lane >> 2, ll = lane & 3;

    float c[2][4][4] = {};

    for (int kc = 0; kc < 16; kc++) {
        __syncthreads();
        // As: 128 rows x 128B, src row = g_X row (512 words) + kc*32
        #pragma unroll
        for (int it = 0; it < 4; it++) {
            int idx = t + it * 256;
            int r = idx >> 3, cc = (idx & 7) * 4;
            *(uint4*)(As + r * 36 + cc) =
                *(const uint4*)(A + (size_t)(m0 + r) * 512 + kc * 32 + cc);
        }
        // Ws: 64 rows x 128B, src row = WT row (512 words) + kc*32
        #pragma unroll
        for (int it = 0; it < 2; it++) {
            int idx = t + it * 256;
            int e = idx >> 3, cc = (idx & 7) * 4;
            *(uint4*)(Ws + e * 36 + cc) =
                *(const uint4*)(WT + (size_t)e * 512 + kc * 32 + cc);
        }
        __syncthreads();

        #pragma unroll
        for (int ks = 0; ks < 4; ks++) {
            const int kb = ks * 8 + ll;
            uint32_t a[2][4];
            #pragma unroll
            for (int mt = 0; mt < 2; mt++) {
                int row = m0w + mt * 16 + lq;
                a[mt][0] = As[row * 36 + kb];
                a[mt][1] = As[(row + 8) * 36 + kb];
                a[mt][2] = As[row * 36 + kb + 4];
                a[mt][3] = As[(row + 8) * 36 + kb + 4];
            }
            #pragma unroll
            for (int nt = 0; nt < 4; nt++) {
                int n = n0w + nt * 8 + lq;
                uint32_t b0 = Ws[n * 36 + kb];
                uint32_t b1 = Ws[n * 36 + kb + 4];
                mma_f16(c[0][nt], a[0], b0, b1);
                mma_f16(c[1][nt], a[1], b0, b1);
            }
        }
    }

    if (z == 2) {
        // V: key-pair interleaved [s/2][e][2] halves
        __half* oh = (__half*)out;
        #pragma unroll
        for (int mt = 0; mt < 2; mt++) {
            #pragma unroll
            for (int nt = 0; nt < 4; nt++) {
                int col = n0w + nt * 8 + 2 * ll;
                float b0 = biasp[col], b1 = biasp[col + 1];
                #pragma unroll
                for (int rr = 0; rr < 2; rr++) {
                    int s = m0 + m0w + mt * 16 + lq + rr * 8;
                    size_t base = (size_t)(s >> 1) * 128 + (s & 1);
                    oh[base + col * 2] =
                        __float2half_rn(c[mt][nt][rr * 2 + 0] + b0);
                    oh[base + (col + 1) * 2] =
                        __float2half_rn(c[mt][nt][rr * 2 + 1] + b1);
                }
            }
        }
    } else {
        #pragma unroll
        for (int mt = 0; mt < 2; mt++) {
            #pragma unroll
            for (int nt = 0; nt < 4; nt++) {
                int col = n0w + nt * 8 + 2 * ll;
                float b0 = biasp[col], b1 = biasp[col + 1];
                #pragma unroll
                for (int rr = 0; rr < 2; rr++) {
                    int s = m0 + m0w + mt * 16 + lq + rr * 8;
                    out[(size_t)s * 32 + (col >> 1)] =
                        pkh2(c[mt][nt][rr * 2 + 0] + b0,
                             c[mt][nt][rr * 2 + 1] + b1);
                }
            }
        }
    }
}

// ---------------------------------------------------------------------------
// Output projection, fp16. Chunk kc == head (gather from g_O). f32 output.
// ---------------------------------------------------------------------------
__global__ __launch_bounds__(256, 1) void outproj_mma_kernel(
    const float* __restrict__ bo, float* __restrict__ Cout)
{
    extern __shared__ uint32_t sm[];
    uint32_t* As = sm;
    uint32_t* Ws = sm + 128 * 36;

    const int m0 = blockIdx.x * 128;
    const int n0 = blockIdx.y * 64;
    const uint32_t* WT = g_WT + (size_t)(48 + blockIdx.y) * 32768;
    const float* biasp = bo + n0;

    const int t = threadIdx.x, wid = t >> 5, lane = t & 31;
    const int m0w = (wid >> 1) * 32, n0w = (wid & 1) * 32;
    const int lq = lane >> 2, ll = lane & 3;

    float c[2][4][4] = {};

    for (int kc = 0; kc < 16; kc++) {
        const uint32_t* A = g_O + (size_t)kc * SS * 32;  // head kc, 32 words/row
        __syncthreads();
        #pragma unroll
        for (int it = 0; it < 4; it++) {
            int idx = t + it * 256;
            int r = idx >> 3, cc = (idx & 7) * 4;
            *(uint4*)(As + r * 36 + cc) =
                *(const uint4*)(A + (size_t)(m0 + r) * 32 + cc);
        }
        #pragma unroll
        for (int it = 0; it < 2; it++) {
            int idx = t + it * 256;
            int e = idx >> 3, cc = (idx & 7) * 4;
            *(uint4*)(Ws + e * 36 + cc) =
                *(const uint4*)(WT + (size_t)e * 512 + kc * 32 + cc);
        }
        __syncthreads();

        #pragma unroll
        for (int ks = 0; ks < 4; ks++) {
            const int kb = ks * 8 + ll;
            uint32_t a[2][4];
            #pragma unroll
            for (int mt = 0; mt < 2; mt++) {
                int row = m0w + mt * 16 + lq;
                a[mt][0] = As[row * 36 + kb];
                a[mt][1] = As[(row + 8) * 36 + kb];
                a[mt][2] = As[row * 36 + kb + 4];
                a[mt][3] = As[(row + 8) * 36 + kb + 4];
            }
            #pragma unroll
            for (int nt = 0; nt < 4; nt++) {
                int n = n0w + nt * 8 + lq;
                uint32_t b0 = Ws[n * 36 + kb];
                uint32_t b1 = Ws[n * 36 + kb + 4];
                mma_f16(c[0][nt], a[0], b0, b1);
                mma_f16(c[1][nt], a[1], b0, b1);
            }
        }
    }

    #pragma unroll
    for (int mt = 0; mt < 2; mt++) {
        int row = m0w + mt * 16 + lq;
        #pragma unroll
        for (int nt = 0; nt < 4; nt++) {
            int col = n0w + nt * 8 + 2 * ll;
            float2 o0 = make_float2(c[mt][nt][0] + biasp[col],
                                    c[mt][nt][1] + biasp[col + 1]);
            float2 o1 = make_float2(c[mt][nt][2] + biasp[col],
                                    c[mt][nt][3] + biasp[col + 1]);
            *(float2*)(Cout + (size_t)(m0 + row) * DD + n0 + col) = o0;
            *(float2*)(Cout + (size_t)(m0 + row + 8) * DD + n0 + col) = o1;
        }
    }
}

// ---------------------------------------------------------------------------
// Flash attention, fp16 m16n8k16, cp.async double-buffered K/V.
// smem (words): Qs[4608] | Ks0[4608] | Ks1[4608] | Vs0[4608] | Vs1[4608]
//   Q/K rows: 64 halves + pad -> 36 words/row (128 rows)
//   V rows:   key-pair kp, 64 half2 + pad -> 72 words/row (64 rows)
// Epilogue reuse: Opart @0 (128x68 f32), lred @8704.
// ---------------------------------------------------------------------------
#define ATTN_SMEM (5 * 4608 * 4)

__global__ __launch_bounds__(256, 1) void attn_kernel()
{
    extern __shared__ uint32_t smu[];
    const uint32_t sb = smem_to_u32(smu);
    uint32_t* Qs = smu;
    uint32_t* Ksb[2] = { smu + 4608, smu + 9216 };
    uint32_t* Vsb[2] = { smu + 13824, smu + 18432 };
    const uint32_t ksw[2] = { sb + 4608 * 4, sb + 9216 * 4 };
    const uint32_t vsw[2] = { sb + 13824 * 4, sb + 18432 * 4 };
    float* Opart = (float*)smu;            // [128][68]
    float* lred  = (float*)(smu + 8704);   // [2][128]

    const int t      = threadIdx.x;
    const int wid    = t >> 5;
    const int lane   = t & 31;
    const int warp_n = wid & 1;
    const int m0w    = (wid >> 1) * 32;
    const int n0w    = warp_n * 64;
    const int lq     = lane >> 2;
    const int ll     = lane & 3;

    const int m0 = blockIdx.x * 128;
    const int h  = blockIdx.y;
    const uint32_t* Qg = g_Q + (size_t)h * SS * 32;
    const uint32_t* Kg = g_K + (size_t)h * SS * 32;
    const uint32_t* Vg = g_V + (size_t)h * SS * 32;

    auto issue_kv = [&](int kb0, int buf) {
        // K: 128 rows x 128B
        #pragma unroll
        for (int it = 0; it < 4; it++) {
            int idx = t + it * 256;
            int r = idx >> 3, cc = (idx & 7) * 4;
            cp16(ksw[buf] + (r * 36 + cc) * 4,
                 Kg + (size_t)(kb0 + r) * 32 + cc);
        }
        // V: 64 kp rows x 256B (g_V row = 64 words)
        #pragma unroll
        for (int it = 0; it < 4; it++) {
            int idx = t + it * 256;
            int r = idx >> 4, cc = (idx & 15) * 4;
            cp16(vsw[buf] + (r * 72 + cc) * 4,
                 Vg + (size_t)((kb0 >> 1) + r) * 64 + cc);
        }
        CP_COMMIT();
    };

    // Q fill
    #pragma unroll
    for (int it = 0; it < 4; it++) {
        int idx = t + it * 256;
        int r = idx >> 3, cc = (idx & 7) * 4;
        cp16(sb + (r * 36 + cc) * 4, Qg + (size_t)(m0 + r) * 32 + cc);
    }
    issue_kv(0, 0);

    float oC[2][8][4];
    #pragma unroll
    for (int mt = 0; mt < 2; mt++)
        #pragma unroll
        for (int nt = 0; nt < 8; nt++)
            #pragma unroll
            for (int i = 0; i < 4; i++) oC[mt][nt][i] = 0.0f;
    float lacc[2][2] = {};

    for (int kt = 0; kt < 32; kt++) {
        const int cur = kt & 1;
        CP_WAIT0();
        __syncthreads();
        if (kt < 31) issue_kv((kt + 1) * 128, cur ^ 1);

        uint32_t* Ks = Ksb[cur];
        uint32_t* Vs = Vsb[cur];

        float sC[2][8][4];
        #pragma unroll
        for (int mt = 0; mt < 2; mt++)
            #pragma unroll
            for (int nt = 0; nt < 8; nt++)
                #pragma unroll
                for (int i = 0; i < 4; i++) sC[mt][nt][i] = 0.0f;

        // S = Q K^T : 4 k16 steps over d=64
        #pragma unroll
        for (int ks = 0; ks < 4; ks++) {
            const int kb = ks * 8 + ll;
            uint32_t a[2][4];
            #pragma unroll
            for (int mt = 0; mt < 2; mt++) {
                int row = m0w + mt * 16 + lq;
                a[mt][0] = Qs[row * 36 + kb];
                a[mt][1] = Qs[(row + 8) * 36 + kb];
                a[mt][2] = Qs[row * 36 + kb + 4];
                a[mt][3] = Qs[(row + 8) * 36 + kb + 4];
            }
            #pragma unroll
            for (int nt = 0; nt < 8; nt++) {
                int key = n0w + nt * 8 + lq;
                uint32_t b0 = Ks[key * 36 + kb];
                uint32_t b1 = Ks[key * 36 + kb + 4];
                mma_f16(sC[0][nt], a[0], b0, b1);
                mma_f16(sC[1][nt], a[1], b0, b1);
            }
        }

        // P = 2^(S * L2E/32), accumulate row sums
        #pragma unroll
        for (int mt = 0; mt < 2; mt++)
            #pragma unroll
            for (int nt = 0; nt < 8; nt++)
                #pragma unroll
                for (int i = 0; i < 4; i++) {
                    float p = ex2f(sC[mt][nt][i] * SCALE_L2E);
                    lacc[mt][i >> 1] += p;
                    sC[mt][nt][i] = p;
                }

        // O += P V : A-frag = packed S C-frags, B from interleaved V
        #pragma unroll
        for (int ks = 0; ks < 4; ks++) {
            uint32_t A0[4] = { pkh2(sC[0][2*ks][0],   sC[0][2*ks][1]),
                               pkh2(sC[0][2*ks][2],   sC[0][2*ks][3]),
                               pkh2(sC[0][2*ks+1][0], sC[0][2*ks+1][1]),
                               pkh2(sC[0][2*ks+1][2], sC[0][2*ks+1][3]) };
            uint32_t A1[4] = { pkh2(sC[1][2*ks][0],   sC[1][2*ks][1]),
                               pkh2(sC[1][2*ks][2],   sC[1][2*ks][3]),
                               pkh2(sC[1][2*ks+1][0], sC[1][2*ks+1][1]),
                               pkh2(sC[1][2*ks+1][2], sC[1][2*ks+1][3]) };
            int vbase = (n0w >> 1) + ks * 8;
            #pragma unroll
            for (int nt2 = 0; nt2 < 8; nt2++) {
                int e = nt2 * 8 + lq;
                uint32_t b0 = Vs[(vbase + ll) * 72 + e];
                uint32_t b1 = Vs[(vbase + ll + 4) * 72 + e];
                mma_f16(oC[0][nt2], A0, b0, b1);
                mma_f16(oC[1][nt2], A1, b0, b1);
            }
        }
    }

    __syncthreads();   // compute done; reuse smem

    #pragma unroll
    for (int mt = 0; mt < 2; mt++)
        #pragma unroll
        for (int half = 0; half < 2; half++) {
            float ls = lacc[mt][half];
            ls += __shfl_xor_sync(0xffffffffu, ls, 1);
            ls += __shfl_xor_sync(0xffffffffu, ls, 2);
            if (ll == 0) {
                int row = m0w + mt * 16 + half * 8 + lq;
                lred[warp_n * 128 + row] = ls;
            }
        }
    if (warp_n == 1) {
        #pragma unroll
        for (int mt = 0; mt < 2; mt++)
            #pragma unroll
            for (int nt2 = 0; nt2 < 8; nt2++) {
                int row = m0w + mt * 16 + lq;
                int col = nt2 * 8 + 2 * ll;
                *(float2*)(Opart + row * 68 + col) =
                    make_float2(oC[mt][nt2][0], oC[mt][nt2][1]);
                *(float2*)(Opart + (row + 8) * 68 + col) =
                    make_float2(oC[mt][nt2][2], oC[mt][nt2][3]);
            }
    }
    __syncthreads();

    if (warp_n == 0) {
        uint32_t* Og = g_O + (size_t)h * SS * 32;
        #pragma unroll
        for (int mt = 0; mt < 2; mt++) {
            int row = m0w + mt * 16 + lq;
            float li0 = 1.0f / (lred[row] + lred[128 + row]);
            float li1 = 1.0f / (lred[row + 8] + lred[128 + row + 8]);
            #pragma unroll
            for (int nt2 = 0; nt2 < 8; nt2++) {
                int col = nt2 * 8 + 2 * ll;
                float2 p0 = *(float2*)(Opart + row * 68 + col);
                float2 p1 = *(float2*)(Opart + (row + 8) * 68 + col);
                Og[(size_t)(m0 + row) * 32 + (col >> 1)] =
                    pkh2((oC[mt][nt2][0] + p0.x) * li0,
                         (oC[mt][nt2][1] + p0.y) * li0);
                Og[(size_t)(m0 + row + 8) * 32 + (col >> 1)] =
                    pkh2((oC[mt][nt2][2] + p1.x) * li1,
                         (oC[mt][nt2][3] + p1.y) * li1);
            }
        }
    }
}

// ---------------------------------------------------------------------------
extern "C" void kernel_launch(void* const* d_in, const int* in_sizes, int n_in,
                              void* d_out, int out_size)
{
    const float* q  = (const float*)d_in[0];
    const float* k  = (const float*)d_in[1];
    const float* v  = (const float*)d_in[2];
    const float* Wq = (const float*)d_in[3];
    const float* bq = (const float*)d_in[4];
    const float* Wk = (const float*)d_in[5];
    const float* bk = (const float*)d_in[6];
    const float* Wv = (const float*)d_in[7];
    const float* bv = (const float*)d_in[8];
    const float* Wo = (const float*)d_in[9];
    const float* bo = (const float*)d_in[10];
    float* out = (float*)d_out;

    preconv<<<1024, 256>>>(q, k, v);
    transpose_w<<<dim3(32, 2, 64), dim3(32, 8)>>>(Wq, Wk, Wv, Wo);

    cudaFuncSetAttribute(proj_mma_kernel,
                         cudaFuncAttributeMaxDynamicSharedMemorySize, PROJ_SMEM);
    proj_mma_kernel<<<dim3(SS / 128, HH, 3), 256, PROJ_SMEM>>>(bq, bk, bv);

    cudaFuncSetAttribute(attn_kernel,
                         cudaFuncAttributeMaxDynamicSharedMemorySize, ATTN_SMEM);
    attn_kernel<<<dim3(SS / 128, HH), 256, ATTN_SMEM>>>();

    cudaFuncSetAttribute(outproj_mma_kernel,
                         cudaFuncAttributeMaxDynamicSharedMemorySize, PROJ_SMEM);
    outproj_mma_kernel<<<dim3(SS / 128, DD / 64), 256, PROJ_SMEM>>>(bo, out);
}